// round 4
// baseline (speedup 1.0000x reference)
#include <cuda_runtime.h>
#include <cuda_bf16.h>
#include <math_constants.h>
#include <climits>
#include <cstdint>

// Problem shape (fixed by setup_inputs)
#define BB 512
#define NN 131072
#define DD 512
#define KK 16

#define CAND_CAP 2048
#define THRESH   0.14f
#define EPS_SCR  3e-3f   // >> bf16 screen error (~1.5e-4)

// ---------------------------------------------------------------------------
// Device-global scratch (allocation-free)
// ---------------------------------------------------------------------------
__device__ __nv_bfloat16  g_mbf[(size_t)NN * DD];       // 128 MiB bf16 memory
__device__ __nv_bfloat16  g_qbf[(size_t)BB * DD];       // bf16 queries
__device__ float g_qrs[BB];       // 1 / ||q_b||
__device__ float g_nb[NN];        // (1 + 0.3*imp[n]) / ||m_n||
__device__ int   g_cand[(size_t)BB * CAND_CAP];
__device__ int   g_candcnt[BB];   // raw atomic counters (may exceed CAND_CAP)
__device__ int   g_flag[BB];      // 1 -> certification failed, brute-force this query
__device__ int   g_topidx[BB * KK];

__device__ __forceinline__ uint32_t smem_u32(const void* p) {
    uint32_t a;
    asm("{ .reg .u64 t; cvta.to.shared.u64 t, %1; cvt.u32.u64 %0, t; }" : "=r"(a) : "l"(p));
    return a;
}

__device__ __forceinline__ void ldmatrix_x4(uint32_t& r0, uint32_t& r1, uint32_t& r2, uint32_t& r3,
                                            uint32_t addr) {
    asm volatile("ldmatrix.sync.aligned.m8n8.x4.shared.b16 {%0,%1,%2,%3}, [%4];"
                 : "=r"(r0), "=r"(r1), "=r"(r2), "=r"(r3) : "r"(addr));
}

__device__ __forceinline__ void mma_bf16(float* c, const uint32_t* a, const uint32_t* b) {
    asm volatile(
        "mma.sync.aligned.m16n8k16.row.col.f32.bf16.bf16.f32 "
        "{%0,%1,%2,%3}, {%4,%5,%6,%7}, {%8,%9}, {%0,%1,%2,%3};"
        : "+f"(c[0]), "+f"(c[1]), "+f"(c[2]), "+f"(c[3])
        : "r"(a[0]), "r"(a[1]), "r"(a[2]), "r"(a[3]), "r"(b[0]), "r"(b[1]));
}

// ---------------------------------------------------------------------------
// Zero per-run state (graph replays must start clean).
// ---------------------------------------------------------------------------
__global__ void init_kernel() {
    int i = blockIdx.x * blockDim.x + threadIdx.x;
    if (i < BB) { g_candcnt[i] = 0; g_flag[i] = 0; }
}

// ---------------------------------------------------------------------------
// Fused: bf16 conversion + scale precompute (one read of X). Warp per row.
// mode 0 (queries):  scale[row] = 1/||x||
// mode 1 (memory):   scale[row] = (1 + 0.3*imp[row]) / ||x||
// ---------------------------------------------------------------------------
__global__ void conv_norm_kernel(const float* __restrict__ X, __nv_bfloat16* __restrict__ Xb,
                                 float* __restrict__ scale, const float* __restrict__ imp,
                                 int nrows, int mode) {
    const int row  = blockIdx.x * 8 + (threadIdx.x >> 5);
    const int lane = threadIdx.x & 31;
    if (row >= nrows) return;
    const float4* src = (const float4*)(X + (size_t)row * DD);
    float s = 0.0f;
#pragma unroll
    for (int i = 0; i < 4; ++i) {
        float4 f = src[i * 32 + lane];
        s += f.x * f.x + f.y * f.y + f.z * f.z + f.w * f.w;
        __nv_bfloat162 p0 = __floats2bfloat162_rn(f.x, f.y);
        __nv_bfloat162 p1 = __floats2bfloat162_rn(f.z, f.w);
        uint2 u;
        u.x = *(uint32_t*)&p0;
        u.y = *(uint32_t*)&p1;
        *(uint2*)(Xb + (size_t)row * DD + (size_t)(i * 32 + lane) * 4) = u;
    }
#pragma unroll
    for (int o = 16; o > 0; o >>= 1) s += __shfl_xor_sync(0xffffffffu, s, o);
    if (lane == 0) {
        float nrm = sqrtf(s);
        if (mode == 0) scale[row] = 1.0f / nrm;
        else           scale[row] = (1.0f + 0.3f * imp[row]) / nrm;
    }
}

// ---------------------------------------------------------------------------
// bf16 HMMA GEMM (NT) with fused threshold-scan epilogue.
// CTA tile 128x128, 8 warps 4(M)x2(N), warp tile 32x64, K-block 32,
// double-buffered smem. Epilogue: v = dot*qrs[b]*nb[n]; if v > THRESH,
// push n into the per-query candidate list. No sims matrix is materialized.
// ---------------------------------------------------------------------------
#define KBLK 32
#define NKB  (DD / KBLK)   // 16
#define APAD 40

__global__ __launch_bounds__(256)
void gemm_scan_kernel() {
    __shared__ __align__(16) __nv_bfloat16 As[2][128][APAD];
    __shared__ __align__(16) __nv_bfloat16 Bs[2][128][APAD];

    const int tid  = threadIdx.x;
    const int warp = tid >> 5;
    const int lane = tid & 31;
    const int wm = warp & 3;   // M position (0..3) -> rows wm*32
    const int wn = warp >> 2;  // N position (0..1) -> cols wn*64

    const int b0 = blockIdx.x * 128;
    const int n0 = blockIdx.y * 128;

    const __nv_bfloat16* Abase = g_qbf + (size_t)b0 * DD;
    const __nv_bfloat16* Bbase = g_mbf + (size_t)n0 * DD;

    const int grow = tid >> 2;        // 0..63
    const int gcol = (tid & 3) * 8;

    float acc[2][8][4];
#pragma unroll
    for (int mt = 0; mt < 2; ++mt)
#pragma unroll
        for (int nt = 0; nt < 8; ++nt)
#pragma unroll
            for (int r = 0; r < 4; ++r) acc[mt][nt][r] = 0.0f;

    {
        uint4 a0 = *(const uint4*)(Abase + (size_t)grow * DD + gcol);
        uint4 a1 = *(const uint4*)(Abase + (size_t)(grow + 64) * DD + gcol);
        uint4 bq0 = *(const uint4*)(Bbase + (size_t)grow * DD + gcol);
        uint4 bq1 = *(const uint4*)(Bbase + (size_t)(grow + 64) * DD + gcol);
        *(uint4*)&As[0][grow][gcol]      = a0;
        *(uint4*)&As[0][grow + 64][gcol] = a1;
        *(uint4*)&Bs[0][grow][gcol]      = bq0;
        *(uint4*)&Bs[0][grow + 64][gcol] = bq1;
    }
    __syncthreads();

    const uint32_t sA = smem_u32(&As[0][0][0]);
    const uint32_t sB = smem_u32(&Bs[0][0][0]);
    const uint32_t bufstride = 128 * APAD * 2;

    for (int kt = 0; kt < NKB; ++kt) {
        const int cur = kt & 1;
        uint4 a0, a1, bq0, bq1;
        if (kt + 1 < NKB) {
            const int koff = (kt + 1) * KBLK + gcol;
            a0  = *(const uint4*)(Abase + (size_t)grow * DD + koff);
            a1  = *(const uint4*)(Abase + (size_t)(grow + 64) * DD + koff);
            bq0 = *(const uint4*)(Bbase + (size_t)grow * DD + koff);
            bq1 = *(const uint4*)(Bbase + (size_t)(grow + 64) * DD + koff);
        }

#pragma unroll
        for (int ks = 0; ks < 2; ++ks) {
            const int col = ks * 16 + (lane >> 4) * 8;
            const int rbase = lane & 15;
            uint32_t af[2][4];
#pragma unroll
            for (int mt = 0; mt < 2; ++mt) {
                int row = wm * 32 + mt * 16 + rbase;
                uint32_t addr = sA + (uint32_t)cur * bufstride + (uint32_t)(row * APAD + col) * 2;
                ldmatrix_x4(af[mt][0], af[mt][1], af[mt][2], af[mt][3], addr);
            }
            uint32_t bf[8][2];
#pragma unroll
            for (int ng = 0; ng < 4; ++ng) {
                int row = wn * 64 + ng * 16 + rbase;
                uint32_t addr = sB + (uint32_t)cur * bufstride + (uint32_t)(row * APAD + col) * 2;
                uint32_t r0, r1, r2, r3;
                ldmatrix_x4(r0, r1, r2, r3, addr);
                bf[ng * 2 + 0][0] = r0; bf[ng * 2 + 0][1] = r2;
                bf[ng * 2 + 1][0] = r1; bf[ng * 2 + 1][1] = r3;
            }
#pragma unroll
            for (int mt = 0; mt < 2; ++mt)
#pragma unroll
                for (int nt = 0; nt < 8; ++nt)
                    mma_bf16(acc[mt][nt], af[mt], bf[nt]);
        }

        if (kt + 1 < NKB) {
            const int nxt = cur ^ 1;
            __syncthreads();
            *(uint4*)&As[nxt][grow][gcol]      = a0;
            *(uint4*)&As[nxt][grow + 64][gcol] = a1;
            *(uint4*)&Bs[nxt][grow][gcol]      = bq0;
            *(uint4*)&Bs[nxt][grow + 64][gcol] = bq1;
            __syncthreads();
        }
    }

    // Epilogue: threshold scan, push candidates (no sims store)
    const int r0 = lane >> 2;
    const int c0 = (lane & 3) * 2;
#pragma unroll
    for (int mt = 0; mt < 2; ++mt) {
        const int brow0 = b0 + wm * 32 + mt * 16 + r0;
        const float q0 = g_qrs[brow0];
        const float q1 = g_qrs[brow0 + 8];
#pragma unroll
        for (int nt = 0; nt < 8; ++nt) {
            const int n = n0 + wn * 64 + nt * 8 + c0;
            const float nb0 = g_nb[n];
            const float nb1 = g_nb[n + 1];
            float v00 = acc[mt][nt][0] * q0 * nb0;
            float v01 = acc[mt][nt][1] * q0 * nb1;
            float v10 = acc[mt][nt][2] * q1 * nb0;
            float v11 = acc[mt][nt][3] * q1 * nb1;
            if (v00 > THRESH) {
                int s = atomicAdd(&g_candcnt[brow0], 1);
                if (s < CAND_CAP) g_cand[(size_t)brow0 * CAND_CAP + s] = n;
            }
            if (v01 > THRESH) {
                int s = atomicAdd(&g_candcnt[brow0], 1);
                if (s < CAND_CAP) g_cand[(size_t)brow0 * CAND_CAP + s] = n + 1;
            }
            if (v10 > THRESH) {
                int s = atomicAdd(&g_candcnt[brow0 + 8], 1);
                if (s < CAND_CAP) g_cand[(size_t)(brow0 + 8) * CAND_CAP + s] = n;
            }
            if (v11 > THRESH) {
                int s = atomicAdd(&g_candcnt[brow0 + 8], 1);
                if (s < CAND_CAP) g_cand[(size_t)(brow0 + 8) * CAND_CAP + s] = n + 1;
            }
        }
    }
}

// ---------------------------------------------------------------------------
// Exact rescore in double + stable top-16 (val desc, idx asc) + certification.
// Flags the query for brute-force fallback if the candidate set cannot be
// proven to contain the true top-16.
// ---------------------------------------------------------------------------
__global__ void rescore_kernel(const float* __restrict__ Q, const float* __restrict__ M,
                               const float* __restrict__ imp, float* __restrict__ out) {
    const int b = blockIdx.x;
    const int t = threadIdx.x;
    const int w = t >> 5;
    const int lane = t & 31;
    const int raw = g_candcnt[b];
    const int cnt = min(raw, CAND_CAP);

    __shared__ double s_val[CAND_CAP];
    __shared__ int    s_idx[CAND_CAP];

    const float* q = Q + (size_t)b * DD;
    double q2 = 0.0;
    for (int d = lane; d < DD; d += 32) { double x = q[d]; q2 += x * x; }
#pragma unroll
    for (int o = 16; o > 0; o >>= 1) q2 += __shfl_xor_sync(0xffffffffu, q2, o);
    const double qn = sqrt(q2);

    for (int s = w; s < cnt; s += 8) {
        const int idx = g_cand[(size_t)b * CAND_CAP + s];
        const float* m = M + (size_t)idx * DD;
        double dot = 0.0, m2 = 0.0;
        for (int d = lane; d < DD; d += 32) {
            double a = q[d], bb = m[d];
            dot += a * bb;
            m2  += bb * bb;
        }
#pragma unroll
        for (int o = 16; o > 0; o >>= 1) {
            dot += __shfl_xor_sync(0xffffffffu, dot, o);
            m2  += __shfl_xor_sync(0xffffffffu, m2, o);
        }
        if (lane == 0) {
            double den = fmax(qn * sqrt(m2), 1e-8);
            s_val[s] = (dot / den) * (1.0 + 0.3 * (double)imp[idx]);
            s_idx[s] = idx;
        }
    }
    __syncthreads();

    if (t == 0) {
        double bv[KK]; int bi[KK];
#pragma unroll
        for (int i = 0; i < KK; ++i) { bv[i] = -CUDART_INF; bi[i] = INT_MAX; }
        for (int s = 0; s < cnt; ++s) {
            double val = s_val[s]; int id = s_idx[s];
            if (val > bv[KK - 1] || (val == bv[KK - 1] && id < bi[KK - 1])) {
                bv[KK - 1] = val; bi[KK - 1] = id;
                for (int p = KK - 1; p >= 1; --p) {
                    bool sw = (bv[p] > bv[p - 1]) || (bv[p] == bv[p - 1] && bi[p] < bi[p - 1]);
                    if (!sw) break;
                    double tv = bv[p]; bv[p] = bv[p - 1]; bv[p - 1] = tv;
                    int    ti = bi[p]; bi[p] = bi[p - 1]; bi[p - 1] = ti;
                }
            }
        }
        // Certification: candidate set provably contains true top-16?
        bool bad = (raw < KK) || (raw > CAND_CAP) ||
                   (bv[KK - 1] < (double)THRESH + (double)EPS_SCR);
        g_flag[b] = bad ? 1 : 0;
        for (int r = 0; r < KK; ++r) {
            out[b * KK + r] = (float)bv[r];
            g_topidx[b * KK + r] = bi[r];
        }
    }
}

// ---------------------------------------------------------------------------
// Brute-force exact fallback (runs only for flagged queries; expected never).
// Block per query: exact f64 sims over all N, per-thread top-16, block merge.
// ---------------------------------------------------------------------------
__global__ void fallback_kernel(const float* __restrict__ Q, const float* __restrict__ M,
                                const float* __restrict__ imp, float* __restrict__ out) {
    const int b = blockIdx.x;
    if (g_flag[b] == 0) return;
    const int t = threadIdx.x;

    __shared__ float s_q[DD];
    for (int d = t; d < DD; d += 256) s_q[d] = Q[(size_t)b * DD + d];
    __syncthreads();

    double q2 = 0.0;
    for (int d = 0; d < DD; ++d) { double x = s_q[d]; q2 += x * x; }
    const double qn = sqrt(q2);

    double v[KK]; int ix[KK];
#pragma unroll
    for (int i = 0; i < KK; ++i) { v[i] = -CUDART_INF; ix[i] = INT_MAX; }

    for (int n = t; n < NN; n += 256) {
        const float* m = M + (size_t)n * DD;
        double dot = 0.0, m2 = 0.0;
        for (int d = 0; d < DD; ++d) {
            double a = s_q[d], bb = m[d];
            dot += a * bb; m2 += bb * bb;
        }
        double den = fmax(qn * sqrt(m2), 1e-8);
        double val = (dot / den) * (1.0 + 0.3 * (double)imp[n]);
        if (val > v[KK - 1]) {
            v[KK - 1] = val; ix[KK - 1] = n;
            for (int p = KK - 1; p >= 1; --p) {
                if (v[p] > v[p - 1]) {
                    double tv = v[p]; v[p] = v[p - 1]; v[p - 1] = tv;
                    int ti = ix[p]; ix[p] = ix[p - 1]; ix[p - 1] = ti;
                }
            }
        }
    }

    __shared__ double rv[256];
    __shared__ int    ri[256];
    for (int round = 0; round < KK; ++round) {
        double bvv = -CUDART_INF; int bii = INT_MAX;
#pragma unroll
        for (int j = 0; j < KK; ++j) {
            bool better = (v[j] > bvv) || (v[j] == bvv && ix[j] < bii);
            if (better) { bvv = v[j]; bii = ix[j]; }
        }
        rv[t] = bvv; ri[t] = bii;
        __syncthreads();
        for (int s = 128; s > 0; s >>= 1) {
            if (t < s) {
                double ov2 = rv[t + s]; int oi2 = ri[t + s];
                if (ov2 > rv[t] || (ov2 == rv[t] && oi2 < ri[t])) { rv[t] = ov2; ri[t] = oi2; }
            }
            __syncthreads();
        }
        if (t == 0) {
            out[b * KK + round] = (float)rv[0];
            g_topidx[b * KK + round] = ri[0];
        }
        int wi = ri[0];
#pragma unroll
        for (int j = 0; j < KK; ++j) {
            if (ix[j] == wi) { v[j] = -CUDART_INF; ix[j] = INT_MAX; }
        }
        __syncthreads();
    }
}

// ---------------------------------------------------------------------------
// Gather memory rows for the final indices.
// ---------------------------------------------------------------------------
__global__ void gather_kernel(const float* __restrict__ M, float* __restrict__ out) {
    const int j = blockIdx.x;
    const int b = blockIdx.y;
    const int idx = g_topidx[b * KK + j];
    const float4* src = (const float4*)(M + (size_t)idx * DD);
    float4* dst = (float4*)(out + (size_t)BB * KK + ((size_t)(b * KK + j)) * DD);
    dst[threadIdx.x] = src[threadIdx.x];
}

// ---------------------------------------------------------------------------
// Launch
// ---------------------------------------------------------------------------
extern "C" void kernel_launch(void* const* d_in, const int* in_sizes, int n_in,
                              void* d_out, int out_size) {
    const float* Q   = (const float*)d_in[0];   // [512, 512]
    const float* M   = (const float*)d_in[1];   // [131072, 512]
    const float* imp = (const float*)d_in[2];   // [131072]
    float* out = (float*)d_out;                 // vals [512,16] ++ gathered [512,16,512]

    __nv_bfloat16 *qbf_ptr, *mbf_ptr;
    float *qrs_ptr, *nb_ptr;
    cudaGetSymbolAddress((void**)&qbf_ptr, g_qbf);
    cudaGetSymbolAddress((void**)&mbf_ptr, g_mbf);
    cudaGetSymbolAddress((void**)&qrs_ptr, g_qrs);
    cudaGetSymbolAddress((void**)&nb_ptr, g_nb);

    init_kernel<<<1, BB>>>();
    conv_norm_kernel<<<BB / 8, 256>>>(Q, qbf_ptr, qrs_ptr, nullptr, BB, 0);
    conv_norm_kernel<<<NN / 8, 256>>>(M, mbf_ptr, nb_ptr, imp, NN, 1);

    dim3 ggrid(BB / 128, NN / 128);   // (4, 1024)
    gemm_scan_kernel<<<ggrid, 256>>>();

    rescore_kernel<<<BB, 256>>>(Q, M, imp, out);
    fallback_kernel<<<BB, 256>>>(Q, M, imp, out);

    dim3 grid_g(KK, BB);
    gather_kernel<<<grid_g, 128>>>(M, out);
}

// round 5
// speedup vs baseline: 4.4375x; 4.4375x over previous
#include <cuda_runtime.h>
#include <cuda_bf16.h>
#include <math_constants.h>
#include <climits>
#include <cstdint>

// Problem shape (fixed by setup_inputs)
#define BB 512
#define NN 131072
#define DD 512
#define KK 16

#define CAND_CAP 2048
#define THRESH   0.14f
#define EPS_SCR  3e-3f   // >> bf16 screen error (~1.5e-4) + f32 rescore noise (~1e-6)

// ---------------------------------------------------------------------------
// Device-global scratch (allocation-free)
// ---------------------------------------------------------------------------
__device__ __nv_bfloat16  g_mbf[(size_t)NN * DD];       // 128 MiB bf16 memory
__device__ __nv_bfloat16  g_qbf[(size_t)BB * DD];       // bf16 queries
__device__ float g_qrs[BB];       // 1 / ||q_b||
__device__ float g_nb[NN];        // (1 + 0.3*imp[n]) / ||m_n||
__device__ int   g_cand[(size_t)BB * CAND_CAP];
__device__ int   g_candcnt[BB];   // raw atomic counters (may exceed CAND_CAP)
__device__ int   g_flag[BB];      // 1 -> certification failed, brute-force this query
__device__ int   g_topidx[BB * KK];

__device__ __forceinline__ uint32_t smem_u32(const void* p) {
    uint32_t a;
    asm("{ .reg .u64 t; cvta.to.shared.u64 t, %1; cvt.u32.u64 %0, t; }" : "=r"(a) : "l"(p));
    return a;
}

__device__ __forceinline__ void ldmatrix_x4(uint32_t& r0, uint32_t& r1, uint32_t& r2, uint32_t& r3,
                                            uint32_t addr) {
    asm volatile("ldmatrix.sync.aligned.m8n8.x4.shared.b16 {%0,%1,%2,%3}, [%4];"
                 : "=r"(r0), "=r"(r1), "=r"(r2), "=r"(r3) : "r"(addr));
}

__device__ __forceinline__ void mma_bf16(float* c, const uint32_t* a, const uint32_t* b) {
    asm volatile(
        "mma.sync.aligned.m16n8k16.row.col.f32.bf16.bf16.f32 "
        "{%0,%1,%2,%3}, {%4,%5,%6,%7}, {%8,%9}, {%0,%1,%2,%3};"
        : "+f"(c[0]), "+f"(c[1]), "+f"(c[2]), "+f"(c[3])
        : "r"(a[0]), "r"(a[1]), "r"(a[2]), "r"(a[3]), "r"(b[0]), "r"(b[1]));
}

// ---------------------------------------------------------------------------
// Zero per-run state (graph replays must start clean).
// ---------------------------------------------------------------------------
__global__ void init_kernel() {
    int i = blockIdx.x * blockDim.x + threadIdx.x;
    if (i < BB) { g_candcnt[i] = 0; g_flag[i] = 0; }
}

// ---------------------------------------------------------------------------
// Fused: bf16 conversion + scale precompute (one read of X). Warp per row.
// mode 0 (queries):  scale[row] = 1/||x||
// mode 1 (memory):   scale[row] = (1 + 0.3*imp[row]) / ||x||
// ---------------------------------------------------------------------------
__global__ void conv_norm_kernel(const float* __restrict__ X, __nv_bfloat16* __restrict__ Xb,
                                 float* __restrict__ scale, const float* __restrict__ imp,
                                 int nrows, int mode) {
    const int row  = blockIdx.x * 8 + (threadIdx.x >> 5);
    const int lane = threadIdx.x & 31;
    if (row >= nrows) return;
    const float4* src = (const float4*)(X + (size_t)row * DD);
    float s = 0.0f;
#pragma unroll
    for (int i = 0; i < 4; ++i) {
        float4 f = src[i * 32 + lane];
        s += f.x * f.x + f.y * f.y + f.z * f.z + f.w * f.w;
        __nv_bfloat162 p0 = __floats2bfloat162_rn(f.x, f.y);
        __nv_bfloat162 p1 = __floats2bfloat162_rn(f.z, f.w);
        uint2 u;
        u.x = *(uint32_t*)&p0;
        u.y = *(uint32_t*)&p1;
        *(uint2*)(Xb + (size_t)row * DD + (size_t)(i * 32 + lane) * 4) = u;
    }
#pragma unroll
    for (int o = 16; o > 0; o >>= 1) s += __shfl_xor_sync(0xffffffffu, s, o);
    if (lane == 0) {
        float nrm = sqrtf(s);
        if (mode == 0) scale[row] = 1.0f / nrm;
        else           scale[row] = (1.0f + 0.3f * imp[row]) / nrm;
    }
}

// ---------------------------------------------------------------------------
// bf16 HMMA GEMM (NT) with fused threshold-scan epilogue.
// CTA tile 128x128, 8 warps 4(M)x2(N), warp tile 32x64, K-block 32,
// double-buffered smem. Epilogue: v = dot*qrs[b]*nb[n]; if v > THRESH,
// push n into the per-query candidate list. No sims matrix is materialized.
// ---------------------------------------------------------------------------
#define KBLK 32
#define NKB  (DD / KBLK)   // 16
#define APAD 40

__global__ __launch_bounds__(256)
void gemm_scan_kernel() {
    __shared__ __align__(16) __nv_bfloat16 As[2][128][APAD];
    __shared__ __align__(16) __nv_bfloat16 Bs[2][128][APAD];

    const int tid  = threadIdx.x;
    const int warp = tid >> 5;
    const int lane = tid & 31;
    const int wm = warp & 3;   // M position (0..3) -> rows wm*32
    const int wn = warp >> 2;  // N position (0..1) -> cols wn*64

    const int b0 = blockIdx.x * 128;
    const int n0 = blockIdx.y * 128;

    const __nv_bfloat16* Abase = g_qbf + (size_t)b0 * DD;
    const __nv_bfloat16* Bbase = g_mbf + (size_t)n0 * DD;

    const int grow = tid >> 2;        // 0..63
    const int gcol = (tid & 3) * 8;

    float acc[2][8][4];
#pragma unroll
    for (int mt = 0; mt < 2; ++mt)
#pragma unroll
        for (int nt = 0; nt < 8; ++nt)
#pragma unroll
            for (int r = 0; r < 4; ++r) acc[mt][nt][r] = 0.0f;

    {
        uint4 a0 = *(const uint4*)(Abase + (size_t)grow * DD + gcol);
        uint4 a1 = *(const uint4*)(Abase + (size_t)(grow + 64) * DD + gcol);
        uint4 bq0 = *(const uint4*)(Bbase + (size_t)grow * DD + gcol);
        uint4 bq1 = *(const uint4*)(Bbase + (size_t)(grow + 64) * DD + gcol);
        *(uint4*)&As[0][grow][gcol]      = a0;
        *(uint4*)&As[0][grow + 64][gcol] = a1;
        *(uint4*)&Bs[0][grow][gcol]      = bq0;
        *(uint4*)&Bs[0][grow + 64][gcol] = bq1;
    }
    __syncthreads();

    const uint32_t sA = smem_u32(&As[0][0][0]);
    const uint32_t sB = smem_u32(&Bs[0][0][0]);
    const uint32_t bufstride = 128 * APAD * 2;

    for (int kt = 0; kt < NKB; ++kt) {
        const int cur = kt & 1;
        uint4 a0, a1, bq0, bq1;
        if (kt + 1 < NKB) {
            const int koff = (kt + 1) * KBLK + gcol;
            a0  = *(const uint4*)(Abase + (size_t)grow * DD + koff);
            a1  = *(const uint4*)(Abase + (size_t)(grow + 64) * DD + koff);
            bq0 = *(const uint4*)(Bbase + (size_t)grow * DD + koff);
            bq1 = *(const uint4*)(Bbase + (size_t)(grow + 64) * DD + koff);
        }

#pragma unroll
        for (int ks = 0; ks < 2; ++ks) {
            const int col = ks * 16 + (lane >> 4) * 8;
            const int rbase = lane & 15;
            uint32_t af[2][4];
#pragma unroll
            for (int mt = 0; mt < 2; ++mt) {
                int row = wm * 32 + mt * 16 + rbase;
                uint32_t addr = sA + (uint32_t)cur * bufstride + (uint32_t)(row * APAD + col) * 2;
                ldmatrix_x4(af[mt][0], af[mt][1], af[mt][2], af[mt][3], addr);
            }
            uint32_t bf[8][2];
#pragma unroll
            for (int ng = 0; ng < 4; ++ng) {
                int row = wn * 64 + ng * 16 + rbase;
                uint32_t addr = sB + (uint32_t)cur * bufstride + (uint32_t)(row * APAD + col) * 2;
                uint32_t r0, r1, r2, r3;
                ldmatrix_x4(r0, r1, r2, r3, addr);
                bf[ng * 2 + 0][0] = r0; bf[ng * 2 + 0][1] = r2;
                bf[ng * 2 + 1][0] = r1; bf[ng * 2 + 1][1] = r3;
            }
#pragma unroll
            for (int mt = 0; mt < 2; ++mt)
#pragma unroll
                for (int nt = 0; nt < 8; ++nt)
                    mma_bf16(acc[mt][nt], af[mt], bf[nt]);
        }

        if (kt + 1 < NKB) {
            const int nxt = cur ^ 1;
            __syncthreads();
            *(uint4*)&As[nxt][grow][gcol]      = a0;
            *(uint4*)&As[nxt][grow + 64][gcol] = a1;
            *(uint4*)&Bs[nxt][grow][gcol]      = bq0;
            *(uint4*)&Bs[nxt][grow + 64][gcol] = bq1;
            __syncthreads();
        }
    }

    // Epilogue: threshold scan, push candidates (no sims store)
    const int r0 = lane >> 2;
    const int c0 = (lane & 3) * 2;
#pragma unroll
    for (int mt = 0; mt < 2; ++mt) {
        const int brow0 = b0 + wm * 32 + mt * 16 + r0;
        const float q0 = g_qrs[brow0];
        const float q1 = g_qrs[brow0 + 8];
#pragma unroll
        for (int nt = 0; nt < 8; ++nt) {
            const int n = n0 + wn * 64 + nt * 8 + c0;
            const float nb0 = g_nb[n];
            const float nb1 = g_nb[n + 1];
            float v00 = acc[mt][nt][0] * q0 * nb0;
            float v01 = acc[mt][nt][1] * q0 * nb1;
            float v10 = acc[mt][nt][2] * q1 * nb0;
            float v11 = acc[mt][nt][3] * q1 * nb1;
            if (v00 > THRESH) {
                int s = atomicAdd(&g_candcnt[brow0], 1);
                if (s < CAND_CAP) g_cand[(size_t)brow0 * CAND_CAP + s] = n;
            }
            if (v01 > THRESH) {
                int s = atomicAdd(&g_candcnt[brow0], 1);
                if (s < CAND_CAP) g_cand[(size_t)brow0 * CAND_CAP + s] = n + 1;
            }
            if (v10 > THRESH) {
                int s = atomicAdd(&g_candcnt[brow0 + 8], 1);
                if (s < CAND_CAP) g_cand[(size_t)(brow0 + 8) * CAND_CAP + s] = n;
            }
            if (v11 > THRESH) {
                int s = atomicAdd(&g_candcnt[brow0 + 8], 1);
                if (s < CAND_CAP) g_cand[(size_t)(brow0 + 8) * CAND_CAP + s] = n + 1;
            }
        }
    }
}

// ---------------------------------------------------------------------------
// Exact f32 rescore (reference op order) + stable top-16 (val desc, idx asc)
// + certification. FP64 is nerfed on B300 (DFMA rt ~18.4/SM) - f32 only.
// ---------------------------------------------------------------------------
__global__ void rescore_kernel(const float* __restrict__ Q, const float* __restrict__ M,
                               const float* __restrict__ imp, float* __restrict__ out) {
    const int b = blockIdx.x;
    const int t = threadIdx.x;
    const int w = t >> 5;
    const int lane = t & 31;
    const int raw = g_candcnt[b];
    const int cnt = min(raw, CAND_CAP);

    __shared__ float s_val[CAND_CAP];
    __shared__ int   s_idx[CAND_CAP];
    __shared__ float s_q[DD];

    for (int d = t; d < DD; d += 256) s_q[d] = Q[(size_t)b * DD + d];
    __syncthreads();

    float q2 = 0.0f;
    for (int d = lane; d < DD; d += 32) { float x = s_q[d]; q2 = fmaf(x, x, q2); }
#pragma unroll
    for (int o = 16; o > 0; o >>= 1) q2 += __shfl_xor_sync(0xffffffffu, q2, o);
    const float qn = sqrtf(q2);

    for (int s = w; s < cnt; s += 8) {
        const int idx = g_cand[(size_t)b * CAND_CAP + s];
        const float4* m = (const float4*)(M + (size_t)idx * DD);
        float dot = 0.0f, m2 = 0.0f;
#pragma unroll
        for (int i = 0; i < 4; ++i) {
            float4 mv = m[i * 32 + lane];
            const float* qp = &s_q[(i * 32 + lane) * 4];
            dot = fmaf(mv.x, qp[0], dot); dot = fmaf(mv.y, qp[1], dot);
            dot = fmaf(mv.z, qp[2], dot); dot = fmaf(mv.w, qp[3], dot);
            m2  = fmaf(mv.x, mv.x, m2);   m2  = fmaf(mv.y, mv.y, m2);
            m2  = fmaf(mv.z, mv.z, m2);   m2  = fmaf(mv.w, mv.w, m2);
        }
#pragma unroll
        for (int o = 16; o > 0; o >>= 1) {
            dot += __shfl_xor_sync(0xffffffffu, dot, o);
            m2  += __shfl_xor_sync(0xffffffffu, m2, o);
        }
        if (lane == 0) {
            float den = fmaxf(qn * sqrtf(m2), 1e-8f);
            s_val[s] = (dot / den) * (1.0f + 0.3f * imp[idx]);
            s_idx[s] = idx;
        }
    }
    __syncthreads();

    if (t == 0) {
        float bv[KK]; int bi[KK];
#pragma unroll
        for (int i = 0; i < KK; ++i) { bv[i] = -CUDART_INF_F; bi[i] = INT_MAX; }
        for (int s = 0; s < cnt; ++s) {
            float val = s_val[s]; int id = s_idx[s];
            if (val > bv[KK - 1] || (val == bv[KK - 1] && id < bi[KK - 1])) {
                bv[KK - 1] = val; bi[KK - 1] = id;
                for (int p = KK - 1; p >= 1; --p) {
                    bool sw = (bv[p] > bv[p - 1]) || (bv[p] == bv[p - 1] && bi[p] < bi[p - 1]);
                    if (!sw) break;
                    float tv = bv[p]; bv[p] = bv[p - 1]; bv[p - 1] = tv;
                    int   ti = bi[p]; bi[p] = bi[p - 1]; bi[p - 1] = ti;
                }
            }
        }
        // Certification: candidate set provably contains true top-16?
        bool bad = (raw < KK) || (raw > CAND_CAP) ||
                   (bv[KK - 1] < THRESH + EPS_SCR);
        g_flag[b] = bad ? 1 : 0;
        for (int r = 0; r < KK; ++r) {
            out[b * KK + r] = bv[r];
            g_topidx[b * KK + r] = bi[r];
        }
    }
}

// ---------------------------------------------------------------------------
// Brute-force exact f32 fallback (runs only for flagged queries; expected never).
// Block per query: f32 sims over all N, per-thread top-16, block merge.
// ---------------------------------------------------------------------------
__global__ void fallback_kernel(const float* __restrict__ Q, const float* __restrict__ M,
                                const float* __restrict__ imp, float* __restrict__ out) {
    const int b = blockIdx.x;
    if (g_flag[b] == 0) return;
    const int t = threadIdx.x;
    const int lane = t & 31;

    __shared__ float s_q[DD];
    for (int d = t; d < DD; d += 256) s_q[d] = Q[(size_t)b * DD + d];
    __syncthreads();

    float q2 = 0.0f;
    for (int d = lane; d < DD; d += 32) { float x = s_q[d]; q2 = fmaf(x, x, q2); }
#pragma unroll
    for (int o = 16; o > 0; o >>= 1) q2 += __shfl_xor_sync(0xffffffffu, q2, o);
    const float qn = sqrtf(q2);

    float v[KK]; int ix[KK];
#pragma unroll
    for (int i = 0; i < KK; ++i) { v[i] = -CUDART_INF_F; ix[i] = INT_MAX; }

    for (int n = t; n < NN; n += 256) {
        const float* m = M + (size_t)n * DD;
        float dot = 0.0f, m2 = 0.0f;
        for (int d = 0; d < DD; ++d) {
            float a = s_q[d], bb = m[d];
            dot = fmaf(a, bb, dot); m2 = fmaf(bb, bb, m2);
        }
        float den = fmaxf(qn * sqrtf(m2), 1e-8f);
        float val = (dot / den) * (1.0f + 0.3f * imp[n]);
        if (val > v[KK - 1]) {
            v[KK - 1] = val; ix[KK - 1] = n;
            for (int p = KK - 1; p >= 1; --p) {
                if (v[p] > v[p - 1]) {
                    float tv = v[p]; v[p] = v[p - 1]; v[p - 1] = tv;
                    int ti = ix[p]; ix[p] = ix[p - 1]; ix[p - 1] = ti;
                }
            }
        }
    }

    __shared__ float rv[256];
    __shared__ int   ri[256];
    for (int round = 0; round < KK; ++round) {
        float bvv = -CUDART_INF_F; int bii = INT_MAX;
#pragma unroll
        for (int j = 0; j < KK; ++j) {
            bool better = (v[j] > bvv) || (v[j] == bvv && ix[j] < bii);
            if (better) { bvv = v[j]; bii = ix[j]; }
        }
        rv[t] = bvv; ri[t] = bii;
        __syncthreads();
        for (int s = 128; s > 0; s >>= 1) {
            if (t < s) {
                float ov2 = rv[t + s]; int oi2 = ri[t + s];
                if (ov2 > rv[t] || (ov2 == rv[t] && oi2 < ri[t])) { rv[t] = ov2; ri[t] = oi2; }
            }
            __syncthreads();
        }
        if (t == 0) {
            out[b * KK + round] = rv[0];
            g_topidx[b * KK + round] = ri[0];
        }
        int wi = ri[0];
#pragma unroll
        for (int j = 0; j < KK; ++j) {
            if (ix[j] == wi) { v[j] = -CUDART_INF_F; ix[j] = INT_MAX; }
        }
        __syncthreads();
    }
}

// ---------------------------------------------------------------------------
// Gather memory rows for the final indices.
// ---------------------------------------------------------------------------
__global__ void gather_kernel(const float* __restrict__ M, float* __restrict__ out) {
    const int j = blockIdx.x;
    const int b = blockIdx.y;
    const int idx = g_topidx[b * KK + j];
    const float4* src = (const float4*)(M + (size_t)idx * DD);
    float4* dst = (float4*)(out + (size_t)BB * KK + ((size_t)(b * KK + j)) * DD);
    dst[threadIdx.x] = src[threadIdx.x];
}

// ---------------------------------------------------------------------------
// Launch
// ---------------------------------------------------------------------------
extern "C" void kernel_launch(void* const* d_in, const int* in_sizes, int n_in,
                              void* d_out, int out_size) {
    const float* Q   = (const float*)d_in[0];   // [512, 512]
    const float* M   = (const float*)d_in[1];   // [131072, 512]
    const float* imp = (const float*)d_in[2];   // [131072]
    float* out = (float*)d_out;                 // vals [512,16] ++ gathered [512,16,512]

    __nv_bfloat16 *qbf_ptr, *mbf_ptr;
    float *qrs_ptr, *nb_ptr;
    cudaGetSymbolAddress((void**)&qbf_ptr, g_qbf);
    cudaGetSymbolAddress((void**)&mbf_ptr, g_mbf);
    cudaGetSymbolAddress((void**)&qrs_ptr, g_qrs);
    cudaGetSymbolAddress((void**)&nb_ptr, g_nb);

    init_kernel<<<1, BB>>>();
    conv_norm_kernel<<<BB / 8, 256>>>(Q, qbf_ptr, qrs_ptr, nullptr, BB, 0);
    conv_norm_kernel<<<NN / 8, 256>>>(M, mbf_ptr, nb_ptr, imp, NN, 1);

    dim3 ggrid(BB / 128, NN / 128);   // (4, 1024)
    gemm_scan_kernel<<<ggrid, 256>>>();

    rescore_kernel<<<BB, 256>>>(Q, M, imp, out);
    fallback_kernel<<<BB, 256>>>(Q, M, imp, out);

    dim3 grid_g(KK, BB);
    gather_kernel<<<grid_g, 128>>>(M, out);
}